// round 8
// baseline (speedup 1.0000x reference)
#include <cuda_runtime.h>

// QLayerNorm: B=4, S=8192, D=1024, fp32. Warp-per-row, TWO-PASS over x.
// R7 showed hold-row-in-registers (32 payload regs) + occupancy cap = spills.
// Instead: pass 1 streams the row accumulating sum/sumsq (values consumed
// immediately, ~4 float4 in flight); pass 2 reloads x from L1 (4KB/row,
// L1-resident) and writes the fused affine output. Low live-register count
// -> 6 CTAs/SM (48 warps) without spilling.
//
// Reference std recurrence (divisor is ALWAYS a, not the iterate):
//   l1=(a/a+a)*.5 ; l2=(l1/a+a)*.5 ; l3=(l2/a+a)*.5 ; std=(l3/a+a)*.5
// Implemented with inv_a = 1/a computed once (fp32 delta ~1e-7, tol 1e-3).

#define D 1024
#define WARPS_PER_CTA 8
#define THREADS (WARPS_PER_CTA * 32)
#define VPL 8            // float4 accesses per lane (D / (32*4))
#define EPS 5e-05f

__global__ __launch_bounds__(THREADS, 6) void qlayernorm_kernel(
    const float* __restrict__ x,
    const float* __restrict__ weight,
    const float* __restrict__ bias,
    float* __restrict__ out)
{
    const int warp = threadIdx.x >> 5;
    const int lane = threadIdx.x & 31;
    const int row  = blockIdx.x * WARPS_PER_CTA + warp;

    const float4* xr4 = reinterpret_cast<const float4*>(x + (long long)row * D);
    float4*       or4 = reinterpret_cast<float4*>(out + (long long)row * D);
    const float4* w4  = reinterpret_cast<const float4*>(weight);
    const float4* b4  = reinterpret_cast<const float4*>(bias);

    // ---- Pass 1: accumulate sum / sumsq (values consumed immediately) ----
    float s = 0.0f, ss = 0.0f;
    #pragma unroll
    for (int i = 0; i < VPL; i++) {
        float4 v = xr4[i * 32 + lane];
        s  += v.x + v.y + v.z + v.w;
        ss += v.x * v.x + v.y * v.y + v.z * v.z + v.w * v.w;
    }

    // Butterfly reduction: every lane ends with the full row sums
    #pragma unroll
    for (int off = 16; off > 0; off >>= 1) {
        s  += __shfl_xor_sync(0xFFFFFFFFu, s,  off);
        ss += __shfl_xor_sync(0xFFFFFFFFu, ss, off);
    }

    // Scalar epilogue, redundant per lane
    const float inv_d = 1.0f / (float)D;
    float mean = s * inv_d;
    float var  = ss * inv_d - mean * mean;
    float a = var + EPS;
    float inv_a = 1.0f / a;            // single divide
    float half_a = 0.5f * a;
    float t;
    t = fmaf(a * inv_a, 0.5f, half_a);     // l1 = (a/a + a)*0.5
    t = fmaf(t * inv_a, 0.5f, half_a);     // l2
    t = fmaf(t * inv_a, 0.5f, half_a);     // l3
    t = fmaf(t * inv_a, 0.5f, half_a);     // std
    const float rstd = 1.0f / t;

    // Prevent CSE of pass-2 reloads with pass-1 loads (would re-inflate
    // register payload back to the spilling configuration).
    asm volatile("" ::: "memory");

    // ---- Pass 2: reload x from L1, fused normalize + affine, store ----
    #pragma unroll
    for (int i = 0; i < VPL; i++) {
        const int idx = i * 32 + lane;
        float4 v = xr4[idx];            // L1 hit (row is resident)
        float4 w = w4[idx];
        float4 b = b4[idx];
        float4 o;
        o.x = (v.x - mean) * rstd * w.x + b.x;
        o.y = (v.y - mean) * rstd * w.y + b.y;
        o.z = (v.z - mean) * rstd * w.z + b.z;
        o.w = (v.w - mean) * rstd * w.w + b.w;
        or4[idx] = o;
    }
}

extern "C" void kernel_launch(void* const* d_in, const int* in_sizes, int n_in,
                              void* d_out, int out_size) {
    const float* x      = (const float*)d_in[0];
    const float* weight = (const float*)d_in[1];
    const float* bias   = (const float*)d_in[2];
    float* out          = (float*)d_out;

    const int rows = in_sizes[0] / D;                 // 32768
    const int grid = rows / WARPS_PER_CTA;            // 4096
    qlayernorm_kernel<<<grid, THREADS>>>(x, weight, bias, out);
}

// round 9
// speedup vs baseline: 1.1774x; 1.1774x over previous
#include <cuda_runtime.h>
#include <cstdint>

// QLayerNorm: B=4, S=8192, D=1024, fp32. Warp-per-row + cp.async staging.
// Each warp stages its 4KB row into smem via 8x cp.async.cg 16B per lane
// (fire-and-forget: no destination registers held -> low reg pressure AND
// high MLP). Each lane then reads back ONLY its own smem slots, so a
// per-thread cp.async.wait_all suffices — no __syncthreads, no __syncwarp
// needed for cross-thread data. 32KB smem/CTA caps residency ~7 CTAs/SM.
//
// Reference std recurrence (divisor is ALWAYS a, not the iterate):
//   l1=(a/a+a)*.5 ; l2=(l1/a+a)*.5 ; l3=(l2/a+a)*.5 ; std=(l3/a+a)*.5
// Implemented with inv_a = 1/a computed once (fp32 delta ~1e-7, tol 1e-3).

#define D 1024
#define WARPS_PER_CTA 8
#define THREADS (WARPS_PER_CTA * 32)
#define VPL 8            // float4 per lane (D / (32*4))
#define EPS 5e-05f

__global__ __launch_bounds__(THREADS) void qlayernorm_kernel(
    const float* __restrict__ x,
    const float* __restrict__ weight,
    const float* __restrict__ bias,
    float* __restrict__ out)
{
    __shared__ float4 sh[WARPS_PER_CTA][D / 4];   // 4KB per row, 32KB total

    const int warp = threadIdx.x >> 5;
    const int lane = threadIdx.x & 31;
    const int row  = blockIdx.x * WARPS_PER_CTA + warp;

    const float4* xr4 = reinterpret_cast<const float4*>(x + (long long)row * D);
    float4*       or4 = reinterpret_cast<float4*>(out + (long long)row * D);
    const float4* w4  = reinterpret_cast<const float4*>(weight);
    const float4* b4  = reinterpret_cast<const float4*>(bias);

    // ---- Stage row into smem: 8 async 16B copies per lane, no regs held ----
    #pragma unroll
    for (int i = 0; i < VPL; i++) {
        const int idx = i * 32 + lane;
        uint32_t dst = (uint32_t)__cvta_generic_to_shared(&sh[warp][idx]);
        asm volatile("cp.async.cg.shared.global [%0], [%1], 16;"
                     :: "r"(dst), "l"(xr4 + idx));
    }
    asm volatile("cp.async.commit_group;");
    asm volatile("cp.async.wait_all;" ::: "memory");
    // Each lane only reads its OWN slots back -> no cross-thread sync needed.

    // ---- Pass 1: accumulate sum / sumsq from smem ----
    float s = 0.0f, ss = 0.0f;
    #pragma unroll
    for (int i = 0; i < VPL; i++) {
        float4 v = sh[warp][i * 32 + lane];
        s  += v.x + v.y + v.z + v.w;
        ss += v.x * v.x + v.y * v.y + v.z * v.z + v.w * v.w;
    }

    // Butterfly reduction: every lane ends with the full row sums
    #pragma unroll
    for (int off = 16; off > 0; off >>= 1) {
        s  += __shfl_xor_sync(0xFFFFFFFFu, s,  off);
        ss += __shfl_xor_sync(0xFFFFFFFFu, ss, off);
    }

    // Scalar epilogue, redundant per lane
    const float inv_d = 1.0f / (float)D;
    float mean = s * inv_d;
    float var  = ss * inv_d - mean * mean;
    float a = var + EPS;
    float inv_a = 1.0f / a;            // single divide
    float half_a = 0.5f * a;
    float t;
    t = fmaf(a * inv_a, 0.5f, half_a);     // l1 = (a/a + a)*0.5
    t = fmaf(t * inv_a, 0.5f, half_a);     // l2
    t = fmaf(t * inv_a, 0.5f, half_a);     // l3
    t = fmaf(t * inv_a, 0.5f, half_a);     // std
    const float rstd = 1.0f / t;

    // ---- Pass 2: reread smem, fused normalize + affine, store ----
    #pragma unroll
    for (int i = 0; i < VPL; i++) {
        const int idx = i * 32 + lane;
        float4 v = sh[warp][idx];       // LDS.128, conflict-free
        float4 w = w4[idx];
        float4 b = b4[idx];
        float4 o;
        o.x = (v.x - mean) * rstd * w.x + b.x;
        o.y = (v.y - mean) * rstd * w.y + b.y;
        o.z = (v.z - mean) * rstd * w.z + b.z;
        o.w = (v.w - mean) * rstd * w.w + b.w;
        or4[idx] = o;
    }
}

extern "C" void kernel_launch(void* const* d_in, const int* in_sizes, int n_in,
                              void* d_out, int out_size) {
    const float* x      = (const float*)d_in[0];
    const float* weight = (const float*)d_in[1];
    const float* bias   = (const float*)d_in[2];
    float* out          = (float*)d_out;

    const int rows = in_sizes[0] / D;                 // 32768
    const int grid = rows / WARPS_PER_CTA;            // 4096
    qlayernorm_kernel<<<grid, THREADS>>>(x, weight, bias, out);
}